// round 15
// baseline (speedup 1.0000x reference)
#include <cuda_runtime.h>
#include <cuda_bf16.h>
#include <cstdint>
#include <math.h>

typedef unsigned int u32;

#define Bq 16
#define Lq 196
#define FDq 2048
#define Nq 1000
#define WDq 300
#define HDq 512
#define DDq 5
#define NIMGq 1000
#define TMAXq 5

// ---------------- device scratch ----------------
__device__ __align__(256) float g_biasB[1024];
__device__ __align__(256) float g_queries[1000 * 512];
__device__ __align__(256) float g_scores[16 * 1000 * 196];
__device__ __align__(256) float g_H1[16000 * 512];
__device__ __align__(256) float g_PQ[1000 * 512];
__device__ __align__(256) float g_prop[1000 * 1000];
__device__ __align__(256) float g_hTA[1000 * 80];
__device__ __align__(256) float g_hTB[1000 * 80];
__device__ __align__(256) float g_mpart[8 * 1000 * 80];
__device__ __align__(256) float g_pooled4[4 * 16 * 2048];
__device__ __align__(256) __nv_bfloat16 g_A2[3136 * 4096];   // [hi | lo]
__device__ __align__(256) __nv_bfloat16 g_B2[1024 * 4096];   // [hi | lo]
__device__ __align__(256) __nv_bfloat16 g_Q3[1000 * 1536];
__device__ __align__(256) __nv_bfloat16 g_K3[3136 * 1536];
__device__ __align__(256) __nv_bfloat16 g_attn3[16000 * 640];
__device__ __align__(256) __nv_bfloat16 g_FKT[16 * 512 * 640];
// pipeline control
__device__ u32 g_tick;
__device__ u32 g_kdone[49];
__device__ u32 g_fdone[49];
__device__ u32 g_qdone;
__device__ u32 g_clfdone;
__device__ u32 g_sdone[16];
__device__ u32 g_adone[16];
__device__ u32 g_h1done;
__device__ u32 g_mdone[8];

// ---------------- HMMA m16n8k16 bf16 + ldmatrix + cp.async ----------------
__device__ __forceinline__ void mma16816(float4& c, const u32 a0, const u32 a1,
                                         const u32 a2, const u32 a3,
                                         const u32 b0, const u32 b1) {
    asm volatile(
        "mma.sync.aligned.m16n8k16.row.col.f32.bf16.bf16.f32 "
        "{%0,%1,%2,%3}, {%4,%5,%6,%7}, {%8,%9}, {%0,%1,%2,%3};"
        : "+f"(c.x), "+f"(c.y), "+f"(c.z), "+f"(c.w)
        : "r"(a0), "r"(a1), "r"(a2), "r"(a3), "r"(b0), "r"(b1));
}
__device__ __forceinline__ void ldsm_x4(u32& r0, u32& r1, u32& r2, u32& r3, u32 saddr) {
    asm volatile("ldmatrix.sync.aligned.m8n8.x4.shared.b16 {%0,%1,%2,%3}, [%4];"
        : "=r"(r0), "=r"(r1), "=r"(r2), "=r"(r3) : "r"(saddr));
}
__device__ __forceinline__ void cp16(u32 dst, const void* src) {
    asm volatile("cp.async.cg.shared.global [%0], [%1], 16;" :: "r"(dst), "l"(src));
}
#define CP_COMMIT() asm volatile("cp.async.commit_group;" ::: "memory")

#define HG_STAGE 15360
#define HG_SMEM  61440

__device__ __forceinline__ void emitK3(int r, int cc, float x0, float x1) {
    __nv_bfloat16 h0 = __float2bfloat16(x0);
    __nv_bfloat16 l0 = __float2bfloat16(x0 - __bfloat162float(h0));
    __nv_bfloat16 h1 = __float2bfloat16(x1);
    __nv_bfloat16 l1 = __float2bfloat16(x1 - __bfloat162float(h1));
    __nv_bfloat162 hp, lp;
    hp.x = h0; hp.y = h1; lp.x = l0; lp.y = l1;
    size_t base = (size_t)r * 1536 + cc;
    *reinterpret_cast<__nv_bfloat162*>(&g_K3[base])        = hp;
    *reinterpret_cast<__nv_bfloat162*>(&g_K3[base + 512])  = lp;
    *reinterpret_cast<__nv_bfloat162*>(&g_K3[base + 1024]) = hp;
}
__device__ __forceinline__ void emitFKT(int r, int j, float x0, float x1) {
    int b = r / 196, l = r - b * 196;
    __nv_bfloat16 h0 = __float2bfloat16(x0);
    __nv_bfloat16 l0 = __float2bfloat16(x0 - __bfloat162float(h0));
    __nv_bfloat16 h1 = __float2bfloat16(x1);
    __nv_bfloat16 l1 = __float2bfloat16(x1 - __bfloat162float(h1));
    size_t base0 = ((size_t)b * 512 + j) * 640 + l;
    g_FKT[base0]       = h0;
    g_FKT[base0 + 208] = l0;
    g_FKT[base0 + 416] = h0;
    size_t base1 = base0 + 640;
    g_FKT[base1]       = h1;
    g_FKT[base1 + 208] = l1;
    g_FKT[base1 + 416] = h1;
}

__device__ __forceinline__ int offA_of(int s, int dedup) {
    if (!dedup) return s << 5;
    return (s < 128) ? ((s & 63) << 5) : (2048 + ((s - 128) << 5));
}
__device__ __forceinline__ int offB_of(int s, int dedup) {
    if (!dedup) return s << 5;
    return (s < 64) ? (s << 5) : ((s < 128) ? (2048 + ((s - 64) << 5)) : ((s - 128) << 5));
}

__device__ __forceinline__ void dev_hgemm(char* smraw, int bxv, int byv,
    const __nv_bfloat16* __restrict__ A, int lda,
    const __nv_bfloat16* __restrict__ B, int ldb,
    const float* __restrict__ bias,
    float* __restrict__ C, int ldc,
    int M, int N, int K3, int do_relu, int mode, int dedup)
{
    int tid = threadIdx.x;
    int brow = byv * 64, bcol = bxv * 128;
    int warp = tid >> 5, lane = tid & 31;
    int wm = warp >> 2, wn = warp & 3;
    int grp = lane >> 2, tig = lane & 3;
    int alr = lane & 15, alc = (lane >> 4) & 1;
    int bl8 = lane & 7, bq = lane >> 3;

    int arow = tid >> 2, ak = (tid & 3) * 8;
    int ga_row = min(brow + arow, M - 1);
    const __nv_bfloat16* pa = A + (size_t)ga_row * lda + ak;
    int brw = tid >> 1, bk = (tid & 1) * 16;
    int gb_row = min(bcol + brw, N - 1);
    const __nv_bfloat16* pb = B + (size_t)gb_row * ldb + bk;

    u32 sbase = (u32)__cvta_generic_to_shared(smraw);
    u32 dAa = sbase + arow * 80 + ak * 2;
    u32 dBb = sbase + 5120 + brw * 80 + bk * 2;

    float4 acc[2][4];
#pragma unroll
    for (int i = 0; i < 2; i++)
#pragma unroll
        for (int j = 0; j < 4; j++) acc[i][j] = make_float4(0.f, 0.f, 0.f, 0.f);

    int nk = K3 >> 5;

#pragma unroll
    for (int s = 0; s < 3; s++) {
        u32 st = s * HG_STAGE;
        cp16(dAa + st, pa + offA_of(s, dedup));
        const __nv_bfloat16* qb = pb + offB_of(s, dedup);
        cp16(dBb + st, qb);  cp16(dBb + st + 16, qb + 8);
        CP_COMMIT();
    }

    for (int kt = 0; kt < nk; kt++) {
        int rem = nk - 1 - kt;
        if (rem >= 2)      asm volatile("cp.async.wait_group 2;" ::: "memory");
        else if (rem == 1) asm volatile("cp.async.wait_group 1;" ::: "memory");
        else               asm volatile("cp.async.wait_group 0;" ::: "memory");
        __syncthreads();

        if (kt + 3 < nk) {
            int s = kt + 3;
            u32 st = (s & 3) * HG_STAGE;
            cp16(dAa + st, pa + offA_of(s, dedup));
            const __nv_bfloat16* qb = pb + offB_of(s, dedup);
            cp16(dBb + st, qb);  cp16(dBb + st + 16, qb + 8);
            CP_COMMIT();
        }

        char* stg = smraw + (kt & 3) * HG_STAGE;
        __nv_bfloat16 (*As)[40] = reinterpret_cast<__nv_bfloat16(*)[40]>(stg);
        __nv_bfloat16 (*Bs)[40] = reinterpret_cast<__nv_bfloat16(*)[40]>(stg + 5120);

#pragma unroll
        for (int kk = 0; kk < 32; kk += 16) {
            u32 af[2][4], bfr[4][2];
#pragma unroll
            for (int mi = 0; mi < 2; mi++) {
                u32 sa = (u32)__cvta_generic_to_shared(
                    &As[wm * 32 + mi * 16 + alr][kk + alc * 8]);
                ldsm_x4(af[mi][0], af[mi][1], af[mi][2], af[mi][3], sa);
            }
#pragma unroll
            for (int np = 0; np < 2; np++) {
                u32 sb = (u32)__cvta_generic_to_shared(
                    &Bs[wn * 32 + np * 16 + (bq >> 1) * 8 + bl8][kk + (bq & 1) * 8]);
                ldsm_x4(bfr[np * 2][0], bfr[np * 2][1],
                        bfr[np * 2 + 1][0], bfr[np * 2 + 1][1], sb);
            }
#pragma unroll
            for (int mi = 0; mi < 2; mi++)
#pragma unroll
                for (int ni = 0; ni < 4; ni++)
                    mma16816(acc[mi][ni], af[mi][0], af[mi][1], af[mi][2], af[mi][3],
                             bfr[ni][0], bfr[ni][1]);
        }
    }

    if (mode == 0) {
#pragma unroll
        for (int mi = 0; mi < 2; mi++) {
            int r0 = brow + wm * 32 + mi * 16 + grp;
            int r1 = r0 + 8;
#pragma unroll
            for (int ni = 0; ni < 4; ni++) {
                int cc = bcol + wn * 32 + ni * 8 + tig * 2;
                float b0 = 0.f, b1 = 0.f;
                if (bias) {
                    if (cc < N)     b0 = bias[cc];
                    if (cc + 1 < N) b1 = bias[cc + 1];
                }
                float4 v = acc[mi][ni];
                float vx = v.x + b0, vy = v.y + b1, vz = v.z + b0, vw = v.w + b1;
                if (do_relu) {
                    vx = fmaxf(vx, 0.f); vy = fmaxf(vy, 0.f);
                    vz = fmaxf(vz, 0.f); vw = fmaxf(vw, 0.f);
                }
                if (r0 < M) {
                    if (cc < N)     C[(size_t)r0 * ldc + cc]     = vx;
                    if (cc + 1 < N) C[(size_t)r0 * ldc + cc + 1] = vy;
                }
                if (r1 < M) {
                    if (cc < N)     C[(size_t)r1 * ldc + cc]     = vz;
                    if (cc + 1 < N) C[(size_t)r1 * ldc + cc + 1] = vw;
                }
            }
        }
    } else {
#pragma unroll
        for (int mi = 0; mi < 2; mi++) {
            int r0 = brow + wm * 32 + mi * 16 + grp;
            int r1 = r0 + 8;
#pragma unroll
            for (int ni = 0; ni < 4; ni++) {
                int cc = bcol + wn * 32 + ni * 8 + tig * 2;
                float4 v = acc[mi][ni];
                if (cc < 512) {
                    float b0 = g_biasB[cc], b1 = g_biasB[cc + 1];
                    emitK3(r0, cc, v.x + b0, v.y + b1);
                    emitK3(r1, cc, v.z + b0, v.w + b1);
                } else {
                    int j = cc - 512;
                    emitFKT(r0, j, v.x, v.y);
                    emitFKT(r1, j, v.z, v.w);
                }
            }
        }
    }
}

// ---------------- device f32x2 SGEMM ----------------
typedef float STile[16][128];

__device__ __forceinline__ void dev_sgemm(char* smraw, int bxv, int byv,
    const float* __restrict__ A, int lda,
    const float* __restrict__ B, int ldb,
    const float* __restrict__ bias,
    float* __restrict__ C, int ldc,
    int M, int N, int K, int do_relu)
{
    STile* As = reinterpret_cast<STile*>(smraw);
    STile* Bs = reinterpret_cast<STile*>(smraw + 16384);
    int tid = threadIdx.x;
    int brow = byv * 128;
    int bcol = bxv * 128;

    int a_row = tid >> 1;
    int a_col = (tid & 1) * 8;
    int b_k   = tid >> 4;
    int b_col = (tid & 15) * 8;
    int ty = tid >> 4, tx = tid & 15;

    unsigned long long acc2[8][4];
#pragma unroll
    for (int i = 0; i < 8; i++)
#pragma unroll
        for (int j = 0; j < 4; j++) acc2[i][j] = 0ULL;

    int nk = (K + 15) >> 4;
    float4 pa0, pa1, pb0, pb1;

    {
        pa0 = make_float4(0.f,0.f,0.f,0.f); pa1 = pa0; pb0 = pa0; pb1 = pa0;
        if (brow + a_row < M) {
            const float* p = A + (size_t)(brow + a_row) * lda + a_col;
            if (a_col < K)     pa0 = *reinterpret_cast<const float4*>(p);
            if (a_col + 4 < K) pa1 = *reinterpret_cast<const float4*>(p + 4);
        }
        if (b_k < K) {
            const float* p = B + (size_t)b_k * ldb + bcol + b_col;
            if (bcol + b_col < N)     pb0 = *reinterpret_cast<const float4*>(p);
            if (bcol + b_col + 4 < N) pb1 = *reinterpret_cast<const float4*>(p + 4);
        }
        As[0][a_col+0][a_row] = pa0.x; As[0][a_col+1][a_row] = pa0.y;
        As[0][a_col+2][a_row] = pa0.z; As[0][a_col+3][a_row] = pa0.w;
        As[0][a_col+4][a_row] = pa1.x; As[0][a_col+5][a_row] = pa1.y;
        As[0][a_col+6][a_row] = pa1.z; As[0][a_col+7][a_row] = pa1.w;
        *reinterpret_cast<float4*>(&Bs[0][b_k][b_col])     = pb0;
        *reinterpret_cast<float4*>(&Bs[0][b_k][b_col + 4]) = pb1;
    }
    __syncthreads();

    for (int t = 0; t < nk; t++) {
        int buf = t & 1;
        int nxt = t + 1;
        if (nxt < nk) {
            int k0 = nxt << 4;
            pa0 = make_float4(0.f,0.f,0.f,0.f); pa1 = pa0; pb0 = pa0; pb1 = pa0;
            if (brow + a_row < M) {
                const float* p = A + (size_t)(brow + a_row) * lda + k0 + a_col;
                if (k0 + a_col < K)     pa0 = *reinterpret_cast<const float4*>(p);
                if (k0 + a_col + 4 < K) pa1 = *reinterpret_cast<const float4*>(p + 4);
            }
            if (k0 + b_k < K) {
                const float* p = B + (size_t)(k0 + b_k) * ldb + bcol + b_col;
                if (bcol + b_col < N)     pb0 = *reinterpret_cast<const float4*>(p);
                if (bcol + b_col + 4 < N) pb1 = *reinterpret_cast<const float4*>(p + 4);
            }
        }

#pragma unroll
        for (int kk = 0; kk < 16; kk++) {
            float4 a0 = *reinterpret_cast<const float4*>(&As[buf][kk][ty * 8]);
            float4 a1 = *reinterpret_cast<const float4*>(&As[buf][kk][ty * 8 + 4]);
            ulonglong2 bq0 = *reinterpret_cast<const ulonglong2*>(&Bs[buf][kk][tx * 8]);
            ulonglong2 bq1 = *reinterpret_cast<const ulonglong2*>(&Bs[buf][kk][tx * 8 + 4]);
            unsigned long long bb0 = bq0.x, bb1 = bq0.y, bb2 = bq1.x, bb3 = bq1.y;
            float av[8] = {a0.x, a0.y, a0.z, a0.w, a1.x, a1.y, a1.z, a1.w};
#pragma unroll
            for (int i = 0; i < 8; i++) {
                unsigned long long aa;
                unsigned int ab = __float_as_uint(av[i]);
                asm("mov.b64 %0, {%1, %1};" : "=l"(aa) : "r"(ab));
                asm("fma.rn.f32x2 %0, %1, %2, %0;" : "+l"(acc2[i][0]) : "l"(aa), "l"(bb0));
                asm("fma.rn.f32x2 %0, %1, %2, %0;" : "+l"(acc2[i][1]) : "l"(aa), "l"(bb1));
                asm("fma.rn.f32x2 %0, %1, %2, %0;" : "+l"(acc2[i][2]) : "l"(aa), "l"(bb2));
                asm("fma.rn.f32x2 %0, %1, %2, %0;" : "+l"(acc2[i][3]) : "l"(aa), "l"(bb3));
            }
        }

        if (nxt < nk) {
            int nb = nxt & 1;
            As[nb][a_col+0][a_row] = pa0.x; As[nb][a_col+1][a_row] = pa0.y;
            As[nb][a_col+2][a_row] = pa0.z; As[nb][a_col+3][a_row] = pa0.w;
            As[nb][a_col+4][a_row] = pa1.x; As[nb][a_col+5][a_row] = pa1.y;
            As[nb][a_col+6][a_row] = pa1.z; As[nb][a_col+7][a_row] = pa1.w;
            *reinterpret_cast<float4*>(&Bs[nb][b_k][b_col])     = pb0;
            *reinterpret_cast<float4*>(&Bs[nb][b_k][b_col + 4]) = pb1;
        }
        __syncthreads();
    }

#pragma unroll
    for (int i = 0; i < 8; i++) {
        int r = brow + ty * 8 + i;
        if (r >= M) continue;
#pragma unroll
        for (int j = 0; j < 4; j++) {
            unsigned long long v = acc2[i][j];
            float c0 = __uint_as_float((unsigned int)v);
            float c1 = __uint_as_float((unsigned int)(v >> 32));
            int c = bcol + tx * 8 + j * 2;
            if (c < N) {
                float t = c0;
                if (bias) t += bias[c];
                if (do_relu) t = fmaxf(t, 0.f);
                C[(size_t)r * ldc + c] = t;
            }
            if (c + 1 < N) {
                float t = c1;
                if (bias) t += bias[c + 1];
                if (do_relu) t = fmaxf(t, 0.f);
                C[(size_t)r * ldc + c + 1] = t;
            }
        }
    }
}

// ---------------- MEGA_side device pieces ----------------
__device__ void dev_pooled(const float* __restrict__ feats, int v) {
    int fb = v & 7;
    int rest = v >> 3;
    int b = rest & 15;
    int ch = rest >> 4;
    int f = fb * 256 + threadIdx.x;
    const float* p = feats + ((size_t)b * Lq + ch * 49) * FDq + f;
    float s = 0.f;
#pragma unroll 7
    for (int l = 0; l < 49; l++) s += p[(size_t)l * FDq];
    g_pooled4[((ch * 16) + b) * 2048 + f] = s;
}

__device__ void dev_cvtA2(const float* __restrict__ feats, int v) {
    long long base = (long long)v * 2048 + threadIdx.x;
#pragma unroll
    for (int u = 0; u < 8; u++) {
        long long i = base + u * 256;
        if (i < 3136LL * 4096) {
            int c = (int)(i & 4095);
            long long r = i >> 12;
            int k = c & 2047;
            float x = feats[r * 2048 + k];
            __nv_bfloat16 h = __float2bfloat16(x);
            g_A2[i] = (c >= 2048) ? __float2bfloat16(x - __bfloat162float(h)) : h;
        }
    }
}

__device__ void dev_cvtB2(const float* __restrict__ Wk, const float* __restrict__ Wf1,
                          const float* __restrict__ bk, int v) {
    if (v == 0) {
        for (int t = threadIdx.x; t < 1024; t += 256)
            g_biasB[t] = (t < 512) ? bk[t] : 0.f;
    }
    long long base = (long long)v * 2048 + threadIdx.x;
#pragma unroll
    for (int u = 0; u < 8; u++) {
        long long i = base + u * 256;
        if (i < 1024LL * 4096) {
            int c = (int)(i & 4095);
            int n = (int)(i >> 12);
            int k = c & 2047;
            float x = (n < 512) ? Wk[(size_t)k * 512 + n] : Wf1[(size_t)k * 512 + (n - 512)];
            __nv_bfloat16 h = __float2bfloat16(x);
            g_B2[i] = (c >= 2048) ? __float2bfloat16(x - __bfloat162float(h)) : h;
        }
    }
}

__device__ void dev_fkt_pad(int v) {
    long long base = (long long)v * 2048 + threadIdx.x;
#pragma unroll
    for (int u = 0; u < 8; u++) {
        long long i = base + u * 256;
        if (i < 16LL * 512 * 52) {
            int e = (int)(i % 52);
            long long row = i / 52;
            int pos = (e < 36) ? (e / 12) * 208 + 196 + (e % 12) : 624 + (e - 36);
            g_FKT[row * 640 + pos] = __float2bfloat16(0.f);
        }
    }
}

#define MS_POOLED  512
#define MS_Q       (MS_POOLED + 32)
#define MS_P       (MS_Q + 16)
#define MS_QM      (MS_P + 16)
#define MS_ZERO    (MS_QM + 3907)
#define MS_CVTA    (MS_ZERO + 6272)
#define MS_CVTB    (MS_CVTA + 2048)
#define MS_TOTAL   (MS_CVTB + 208)

__global__ __launch_bounds__(256) void mega_side(const float* __restrict__ feats,
                                                 const float* __restrict__ embed,
                                                 const float* __restrict__ W_query,
                                                 const float* __restrict__ b_query,
                                                 const float* __restrict__ Wr1,
                                                 const float* __restrict__ W_key,
                                                 const float* __restrict__ Wf1,
                                                 const float* __restrict__ b_key) {
    __shared__ __align__(16) char sm[32768];
    int f = blockIdx.x;
    if (f == 0 && threadIdx.x == 0) {
        g_tick = 0; g_qdone = 0; g_clfdone = 0; g_h1done = 0;
        for (int i = 0; i < 49; i++) { g_kdone[i] = 0; g_fdone[i] = 0; }
        for (int i = 0; i < 16; i++) { g_sdone[i] = 0; g_adone[i] = 0; }
        for (int i = 0; i < 8; i++) g_mdone[i] = 0;
    }
    if (f < MS_POOLED) {
        dev_pooled(feats, f);
    } else if (f < MS_Q) {
        int v = f - MS_POOLED;
        dev_sgemm(sm, v & 3, v >> 2, embed, 300, W_query, 512, b_query,
                  g_queries, 512, 1000, 512, 300, 0);
    } else if (f < MS_P) {
        int v = f - MS_Q;
        dev_sgemm(sm, v & 1, v >> 1, embed, 300, Wr1, 256, nullptr,
                  g_PQ, 512, 1000, 256, 300, 0);
    } else if (f < MS_QM) {
        int v = f - MS_P;
        dev_sgemm(sm, v & 1, v >> 1, embed, 300, Wr1 + 300 * 256, 256, nullptr,
                  g_PQ + 256, 512, 1000, 256, 300, 0);
    } else if (f < MS_ZERO) {
        int i = (f - MS_QM) * 256 + threadIdx.x;
        if (i < 1000 * 1000) g_prop[i] = 0.f;
    } else if (f < MS_CVTA) {
        dev_cvtA2(feats, f - MS_ZERO);
    } else if (f < MS_CVTB) {
        dev_cvtB2(W_key, Wf1, b_key, f - MS_CVTA);
    } else {
        dev_fkt_pad(f - MS_CVTB);
    }
}

// ---------------- MEGA_BIG pieces ----------------
__device__ void dev_clf(char* smraw, int v, const float* __restrict__ W_clf,
                        const float* __restrict__ b_clf, float* __restrict__ out_img) {
    float (*sp)[2048] = reinterpret_cast<float(*)[2048]>(smraw);
    int tid = threadIdx.x;
    int bx = v & 3;
    int bg = (v >> 2) * 4;
    for (int i = tid; i < 4 * 2048; i += 256) {
        int g = i >> 11, ff = i & 2047;
        int b = bg + g;
        float s = g_pooled4[(0 * 16 + b) * 2048 + ff] + g_pooled4[(1 * 16 + b) * 2048 + ff]
                + g_pooled4[(2 * 16 + b) * 2048 + ff] + g_pooled4[(3 * 16 + b) * 2048 + ff];
        sp[g][ff] = s * (1.f / 196.f);
    }
    __syncthreads();
    int c = bx * 256 + tid;
    if (c < NIMGq) {
        float a0 = b_clf[c], a1 = a0, a2 = a0, a3 = a0;
#pragma unroll 4
        for (int f = 0; f < 2048; f++) {
            float w = W_clf[(size_t)f * NIMGq + c];
            a0 = fmaf(sp[0][f], w, a0);
            a1 = fmaf(sp[1][f], w, a1);
            a2 = fmaf(sp[2][f], w, a2);
            a3 = fmaf(sp[3][f], w, a3);
        }
        out_img[(bg + 0) * NIMGq + c] = a0;
        out_img[(bg + 1) * NIMGq + c] = a1;
        out_img[(bg + 2) * NIMGq + c] = a2;
        out_img[(bg + 3) * NIMGq + c] = a3;
    }
}

__device__ void dev_cvtQ3(int v) {
    long long base = (long long)v * 2048 + threadIdx.x;
#pragma unroll
    for (int u = 0; u < 8; u++) {
        long long i = base + u * 256;
        if (i < 1000LL * 1536) {
            int c = (int)(i % 1536);
            long long r = i / 1536;
            int seg = c >> 9, k = c & 511;
            float x = g_queries[r * 512 + k];
            __nv_bfloat16 h = __float2bfloat16(x);
            g_Q3[i] = (seg == 2) ? __float2bfloat16(x - __bfloat162float(h)) : h;
        }
    }
}

__device__ void dev_edge(int v, const int* __restrict__ edges, const float* __restrict__ br1,
                         const float* __restrict__ Wr2, const float* __restrict__ br2, int E) {
    int warp = (int)threadIdx.x >> 5;
    int lane = threadIdx.x & 31;
#pragma unroll
    for (int u = 0; u < 8; u++) {
        int e = v * 64 + u * 8 + warp;
        if (e >= E) break;
        int s = edges[e];
        int d = edges[E + e];
        const float* Pr = g_PQ + (size_t)s * 512;
        const float* Qr = g_PQ + (size_t)d * 512 + 256;
        float acc = 0.f;
#pragma unroll
        for (int i = 0; i < 8; i++) {
            int j = lane + 32 * i;
            float h = fmaxf(Pr[j] + Qr[j] + br1[j], 0.f);
            acc = fmaf(h, Wr2[j], acc);
        }
        for (int o = 16; o; o >>= 1) acc += __shfl_xor_sync(0xffffffffu, acc, o);
        if (lane == 0) atomicAdd(&g_prop[(size_t)s * 1000 + d], tanhf(acc + br2[0]));
    }
}

__device__ void dev_softmax1000(char* smraw, int b, float* __restrict__ base) {
    float* sv = reinterpret_cast<float*>(smraw);
    float* red = reinterpret_cast<float*>(smraw) + 1000;
    int tid = threadIdx.x;
    float* row = base + (size_t)b * 1000;
    float m = -1e30f;
    for (int i = tid; i < 1000; i += 256) { float x = row[i]; sv[i] = x; m = fmaxf(m, x); }
    for (int o = 16; o; o >>= 1) m = fmaxf(m, __shfl_xor_sync(0xffffffffu, m, o));
    if ((tid & 31) == 0) red[tid >> 5] = m;
    __syncthreads();
    float bm = red[0];
#pragma unroll
    for (int i = 1; i < 8; i++) bm = fmaxf(bm, red[i]);
    float s = 0.f;
    for (int i = tid; i < 1000; i += 256) { float e = expf(sv[i] - bm); sv[i] = e; s += e; }
    for (int o = 16; o; o >>= 1) s += __shfl_xor_sync(0xffffffffu, s, o);
    __syncthreads();
    if ((tid & 31) == 0) red[tid >> 5] = s;
    __syncthreads();
    float bs = 0.f;
#pragma unroll
    for (int i = 0; i < 8; i++) bs += red[i];
    float inv = 1.f / bs;
    for (int i = tid; i < 1000; i += 256) row[i] = sv[i] * inv;
}

__device__ void dev_softmax196(int v, float* __restrict__ attn) {
    int z = v / 125;
    int vv = v - z * 125;
    int warp = (int)threadIdx.x >> 5;
    int lane = threadIdx.x & 31;
    int gw = z * 1000 + vv * 8 + warp;
    const float* src = g_scores + (size_t)gw * Lq;
    float val[7];
    float m = -1e30f;
#pragma unroll
    for (int i = 0; i < 7; i++) {
        int j = lane + 32 * i;
        val[i] = (j < Lq) ? src[j] : -1e30f;
        m = fmaxf(m, val[i]);
    }
    for (int o = 16; o; o >>= 1) m = fmaxf(m, __shfl_xor_sync(0xffffffffu, m, o));
    float s = 0.f;
#pragma unroll
    for (int i = 0; i < 7; i++) {
        int j = lane + 32 * i;
        val[i] = (j < Lq) ? expf(val[i] - m) : 0.f;
        s += val[i];
    }
    for (int o = 16; o; o >>= 1) s += __shfl_xor_sync(0xffffffffu, s, o);
    float inv = 1.f / s;
    size_t base = (size_t)gw * 640;
#pragma unroll
    for (int i = 0; i < 7; i++) {
        int j = lane + 32 * i;
        if (j < Lq) {
            float e = val[i] * inv;
            attn[(size_t)gw * Lq + j] = e;
            __nv_bfloat16 h = __float2bfloat16(e);
            __nv_bfloat16 lo = __float2bfloat16(e - __bfloat162float(h));
            g_attn3[base + 0 * 208 + j] = h;
            g_attn3[base + 1 * 208 + j] = h;
            g_attn3[base + 2 * 208 + j] = lo;
        }
    }
    __nv_bfloat16 zz = __float2bfloat16(0.f);
#pragma unroll
    for (int e2 = 0; e2 < 2; e2++) {
        int t = lane + e2 * 32;
        if (t < 52) {
            int pos = (t < 36) ? (t / 12) * 208 + 196 + (t % 12) : 624 + (t - 36);
            g_attn3[base + pos] = zz;
        }
    }
}

// h0 -> transposed hidden layout hT[n][b*5+d]
__device__ void dev_h0(int v, const float* __restrict__ Wf2, const float* __restrict__ bf2) {
    int gw = v * 8 + ((int)threadIdx.x >> 5);
    int lane = threadIdx.x & 31;
    if (gw >= 16000) return;
    const float* row = g_H1 + (size_t)gw * 512;
    float acc[5] = {0.f, 0.f, 0.f, 0.f, 0.f};
#pragma unroll
    for (int i = 0; i < 16; i++) {
        int j = lane + 32 * i;
        float vv = row[j];
#pragma unroll
        for (int d = 0; d < 5; d++) acc[d] = fmaf(vv, Wf2[j * 5 + d], acc[d]);
    }
#pragma unroll
    for (int d = 0; d < 5; d++)
        for (int o = 16; o; o >>= 1) acc[d] += __shfl_xor_sync(0xffffffffu, acc[d], o);
    if (lane == 0) {
        int z = gw / 1000, n = gw - z * 1000;
#pragma unroll
        for (int d = 0; d < 5; d++) g_hTA[n * 80 + z * 5 + d] = acc[d] + bf2[d];
    }
}

__device__ __forceinline__ void spin_ge(volatile u32* p, u32 target) {
    while (*p < target) __nanosleep(128);
}

// ticket layout:
// [feats 392][clf 16][cvtQ3 750][edges NE][scores 512][sm1000 16][sm196 2000][H1 1024][h0 2000]
__global__ __launch_bounds__(256) void mega_big(const float* __restrict__ W_clf,
                                                const float* __restrict__ b_clf,
                                                float* __restrict__ out_img,
                                                const int* __restrict__ edges,
                                                const float* __restrict__ br1,
                                                const float* __restrict__ Wr2,
                                                const float* __restrict__ br2,
                                                float* __restrict__ out_attn,
                                                const float* __restrict__ bf1,
                                                const float* __restrict__ Wf2,
                                                const float* __restrict__ bf2,
                                                int E, int NE) {
    extern __shared__ __align__(16) char smdyn[];
    __shared__ u32 s_tick;
    if (threadIdx.x == 0) s_tick = atomicAdd(&g_tick, 1u);
    __syncthreads();
    int f = (int)s_tick;

    int T_CLF = 392 + 16;
    int T_Q    = T_CLF + 750;
    int T_E    = T_Q + NE;
    int T_SC   = T_E + 512;
    int T_SM1K = T_SC + 16;
    int T_SM   = T_SM1K + 2000;
    int T_H1   = T_SM + 1024;

    if (f < 392) {
        int bx = f & 7, by = f >> 3;
        dev_hgemm(smdyn, bx, by, g_A2, 4096, g_B2, 4096, nullptr,
                  nullptr, 0, 3136, 1024, 6144, 0, 1, 1);
        __threadfence();
        __syncthreads();
        if (threadIdx.x == 0) {
            if (bx < 4) atomicAdd(&g_kdone[by], 1u);
            else        atomicAdd(&g_fdone[by], 1u);
        }
    } else if (f < T_CLF) {
        dev_clf(smdyn, f - 392, W_clf, b_clf, out_img);
        __threadfence();
        __syncthreads();
        if (threadIdx.x == 0) atomicAdd(&g_clfdone, 1u);
    } else if (f < T_Q) {
        dev_cvtQ3(f - T_CLF);
        __threadfence();
        __syncthreads();
        if (threadIdx.x == 0) atomicAdd(&g_qdone, 1u);
    } else if (f < T_E) {
        dev_edge(f - T_Q, edges, br1, Wr2, br2, E);
    } else if (f < T_SC) {
        int v = f - T_E;
        int bx = v & 1, by = (v >> 1) & 15, z = v >> 5;
        if (threadIdx.x == 0) {
            spin_ge(&g_qdone, 750u);
            int t0 = (196 * z) >> 6;
            int t3 = (196 * z + 195) >> 6;
            for (int t = t0; t <= t3; t++) spin_ge(&g_kdone[t], 4u);
        }
        __syncthreads();
        __threadfence();
        dev_hgemm(smdyn, bx, by,
                  g_Q3, 1536,
                  g_K3 + (size_t)z * 196 * 1536, 1536, nullptr,
                  g_scores + (size_t)z * 1000 * 196, 196,
                  1000, 196, 1536, 0, 0, 0);
        __threadfence();
        __syncthreads();
        if (threadIdx.x == 0) atomicAdd(&g_sdone[z], 1u);
    } else if (f < T_SM1K) {
        if (threadIdx.x == 0) spin_ge(&g_clfdone, 16u);
        __syncthreads();
        __threadfence();
        dev_softmax1000(smdyn, f - T_SC, out_img);
    } else if (f < T_SM) {
        int v = f - T_SM1K;
        int z = v / 125;
        if (threadIdx.x == 0) spin_ge(&g_sdone[z], 32u);
        __syncthreads();
        __threadfence();
        dev_softmax196(v, out_attn);
        __threadfence();
        __syncthreads();
        if (threadIdx.x == 0) atomicAdd(&g_adone[z], 1u);
    } else if (f < T_H1) {
        int v = f - T_SM;
        int bx = v & 3, by = (v >> 2) & 15, z = v >> 6;
        if (threadIdx.x == 0) {
            spin_ge(&g_adone[z], 125u);
            int t0 = (196 * z) >> 6;
            int t3 = (196 * z + 195) >> 6;
            for (int t = t0; t <= t3; t++) spin_ge(&g_fdone[t], 4u);
        }
        __syncthreads();
        __threadfence();
        dev_hgemm(smdyn, bx, by,
                  g_attn3 + (size_t)z * 1000 * 640, 640,
                  g_FKT + (size_t)z * 512 * 640, 640, bf1,
                  g_H1 + (size_t)z * 1000 * 512, 512,
                  1000, 512, 640, 1, 0, 0);
        __threadfence();
        __syncthreads();
        if (threadIdx.x == 0) atomicAdd(&g_h1done, 1u);
    } else {
        if (threadIdx.x == 0) spin_ge(&g_h1done, 1024u);
        __syncthreads();
        __threadfence();
        dev_h0(f - T_H1, Wf2, bf2);
    }
}

// ---------------- GNN step: split-K GEMM producers + reduce/GRU consumers ----------
// grid: 128 producers (16 n-tiles x 8 k-splits) + 50 consumers; 320 threads.
__global__ __launch_bounds__(320) void msg_gru_step(const float* __restrict__ Wih,
                                                    const float* __restrict__ bih,
                                                    const float* __restrict__ Whh,
                                                    const float* __restrict__ bhh,
                                                    int t) {
    const float* hin = (t & 1) ? g_hTB : g_hTA;
    float* hout = (t & 1) ? g_hTA : g_hTB;
    int f = blockIdx.x;
    int tid = threadIdx.x;

    if (f < 128) {
        __shared__ float sp[64][33];
        __shared__ float sh[32][84];
        int nb = f & 15, kc = f >> 4;
        int n0 = nb * 64, k0 = kc * 125;
        int rg = tid / 20, cg = tid % 20;   // rg 0..15, cg 0..19
        float acc[4][4];
#pragma unroll
        for (int i = 0; i < 4; i++)
#pragma unroll
            for (int j = 0; j < 4; j++) acc[i][j] = 0.f;

        for (int m0 = 0; m0 < 125; m0 += 32) {
            int mlen = min(32, 125 - m0);
            for (int idx = tid; idx < 64 * 32; idx += 320) {
                int r = idx >> 5, c = idx & 31;
                sp[r][c] = (n0 + r < 1000 && c < mlen)
                    ? g_prop[(size_t)(n0 + r) * 1000 + k0 + m0 + c] : 0.f;
            }
            for (int idx = tid; idx < 32 * 80; idx += 320) {
                int mm = idx / 80, c = idx - mm * 80;
                sh[mm][c] = (mm < mlen) ? hin[(size_t)(k0 + m0 + mm) * 80 + c] : 0.f;
            }
            __syncthreads();
#pragma unroll 4
            for (int mm = 0; mm < 32; mm++) {
                float bv[4];
#pragma unroll
                for (int j = 0; j < 4; j++) bv[j] = sh[mm][cg * 4 + j];
#pragma unroll
                for (int i = 0; i < 4; i++) {
                    float a = sp[rg * 4 + i][mm];
#pragma unroll
                    for (int j = 0; j < 4; j++) acc[i][j] = fmaf(a, bv[j], acc[i][j]);
                }
            }
            __syncthreads();
        }
#pragma unroll
        for (int i = 0; i < 4; i++) {
            int row = n0 + rg * 4 + i;
            if (row < 1000) {
#pragma unroll
                for (int j = 0; j < 4; j++)
                    g_mpart[(size_t)kc * 80000 + (size_t)row * 80 + cg * 4 + j] = acc[i][j];
            }
        }
        __threadfence();
        __syncthreads();
        if (tid == 0) atomicAdd(&g_mdone[t], 1u);
    } else {
        if (tid == 0) spin_ge(&g_mdone[t], 128u);
        __syncthreads();
        __threadfence();
        int i = (f - 128) * 320 + tid;
        if (i >= 16000) return;
        int b = i / 1000, n = i - b * 1000;
        int c0 = n * 80 + b * 5;
        float x[5], h[5];
#pragma unroll
        for (int d = 0; d < 5; d++) {
            float s = 0.f;
#pragma unroll
            for (int kc = 0; kc < 8; kc++) s += g_mpart[(size_t)kc * 80000 + c0 + d];
            x[d] = tanhf(s);
            h[d] = hin[c0 + d];
        }
#pragma unroll
        for (int d = 0; d < 5; d++) {
            float ir = bih[d], iz = bih[5 + d], in_ = bih[10 + d];
            float hr = bhh[d], hz = bhh[5 + d], hn = bhh[10 + d];
#pragma unroll
            for (int k = 0; k < 5; k++) {
                ir = fmaf(x[k], Wih[d * 5 + k], ir);
                iz = fmaf(x[k], Wih[(5 + d) * 5 + k], iz);
                in_ = fmaf(x[k], Wih[(10 + d) * 5 + k], in_);
                hr = fmaf(h[k], Whh[d * 5 + k], hr);
                hz = fmaf(h[k], Whh[(5 + d) * 5 + k], hz);
                hn = fmaf(h[k], Whh[(10 + d) * 5 + k], hn);
            }
            float rr = 1.f / (1.f + expf(-(ir + hr)));
            float zz = 1.f / (1.f + expf(-(iz + hz)));
            float nn = tanhf(in_ + rr * hn);
            hout[c0 + d] = (1.f - zz) * nn + zz * h[d];
        }
    }
}

__global__ void out_kernel(const float* __restrict__ Wo1, const float* __restrict__ bo1,
                           const float* __restrict__ Wo2, const float* __restrict__ bo2,
                           float* __restrict__ out) {
    int gw = (blockIdx.x * blockDim.x + threadIdx.x) >> 5;
    int lane = threadIdx.x & 31;
    if (gw >= 16000) return;
    int b = gw / 1000, n = gw - b * 1000;
    float h[5];
#pragma unroll
    for (int d = 0; d < 5; d++) h[d] = g_hTB[n * 80 + b * 5 + d];
    float acc = 0.f;
#pragma unroll
    for (int i = 0; i < 16; i++) {
        int j = lane + 32 * i;
        float t = bo1[j];
#pragma unroll
        for (int d = 0; d < 5; d++) t = fmaf(h[d], Wo1[d * 512 + j], t);
        acc = fmaf(fmaxf(t, 0.f), Wo2[j], acc);
    }
    for (int o = 16; o; o >>= 1) acc += __shfl_xor_sync(0xffffffffu, acc, o);
    if (lane == 0) out[gw] = acc + bo2[0];
}

// ---------------- launcher ----------------
extern "C" void kernel_launch(void* const* d_in, const int* in_sizes, int n_in,
                              void* d_out, int out_size) {
    const float* feats  = (const float*)d_in[0];
    const float* embed  = (const float*)d_in[1];
    const int*   edges  = (const int*)d_in[2];
    const float* W_key  = (const float*)d_in[3];
    const float* b_key  = (const float*)d_in[4];
    const float* W_query= (const float*)d_in[5];
    const float* b_query= (const float*)d_in[6];
    const float* Wf1    = (const float*)d_in[7];
    const float* bf1    = (const float*)d_in[8];
    const float* Wf2    = (const float*)d_in[9];
    const float* bf2    = (const float*)d_in[10];
    const float* Wr1    = (const float*)d_in[11];
    const float* br1    = (const float*)d_in[12];
    const float* Wr2    = (const float*)d_in[13];
    const float* br2    = (const float*)d_in[14];
    const float* Wo1    = (const float*)d_in[15];
    const float* bo1    = (const float*)d_in[16];
    const float* Wo2    = (const float*)d_in[17];
    const float* bo2    = (const float*)d_in[18];
    const float* W_ih   = (const float*)d_in[19];
    const float* b_ih   = (const float*)d_in[20];
    const float* W_hh   = (const float*)d_in[21];
    const float* b_hh   = (const float*)d_in[22];
    const float* W_clf  = (const float*)d_in[23];
    const float* b_clf  = (const float*)d_in[24];

    float* out        = (float*)d_out;
    float* out_logits = out;
    float* out_attn   = out + 16000;
    float* out_img    = out + 16000 + 16 * 1000 * 196;

    int E = in_sizes[2] / 2;
    int NE = (E + 63) / 64;

    static int smem_set = 0;
    if (!smem_set) {
        cudaFuncSetAttribute(mega_big, cudaFuncAttributeMaxDynamicSharedMemorySize, HG_SMEM);
        smem_set = 1;
    }

    // 1. MEGA_side: pooled | queries | P | Qm | zero_prop | cvtA2 | cvtB2 | fkt_pad (+flags)
    mega_side<<<MS_TOTAL, 256>>>(feats, embed, W_query, b_query, Wr1, W_key, Wf1, b_key);
    // 2. MEGA_BIG (ticketed): feats -> K3/FKT | clf | Q3 | edges | scores | sm1000 | sm196 | H1 | h0
    int nbig = 1158 + NE + 512 + 16 + 2000 + 1024 + 2000;
    mega_big<<<nbig, 256, HG_SMEM>>>(W_clf, b_clf, out_img, edges, br1, Wr2, br2,
                                     out_attn, bf1, Wf2, bf2, E, NE);
    // 3-7. GNN steps: split-K msg GEMM + fused reduce/GRU (producers+consumers per launch)
    for (int t = 0; t < TMAXq; t++) {
        msg_gru_step<<<178, 320>>>(W_ih, b_ih, W_hh, b_hh, t);
    }
    // 8. output MLP
    out_kernel<<<2000, 256>>>(Wo1, bo1, Wo2, bo2, out_logits);

    (void)n_in; (void)out_size;
}

// round 16
// speedup vs baseline: 1.4539x; 1.4539x over previous
#include <cuda_runtime.h>
#include <cuda_bf16.h>
#include <cstdint>
#include <math.h>

typedef unsigned int u32;

#define Bq 16
#define Lq 196
#define FDq 2048
#define Nq 1000
#define WDq 300
#define HDq 512
#define DDq 5
#define NIMGq 1000
#define TMAXq 5

// ---------------- device scratch ----------------
__device__ __align__(256) float g_biasB[1024];
__device__ __align__(256) float g_queries[1000 * 512];
__device__ __align__(256) float g_scores[16 * 1000 * 196];
__device__ __align__(256) float g_H1[16000 * 512];
__device__ __align__(256) float g_PQ[1000 * 512];
__device__ __align__(256) float g_prop[1000 * 1000];
__device__ __align__(256) float g_hA[16000 * 5];
__device__ __align__(256) float g_hB[16000 * 5];
__device__ __align__(256) float g_pooled4[4 * 16 * 2048];
__device__ __align__(256) __nv_bfloat16 g_A2[3136 * 4096];   // [hi | lo]
__device__ __align__(256) __nv_bfloat16 g_B2[1024 * 4096];   // [hi | lo]
__device__ __align__(256) __nv_bfloat16 g_Q3[1000 * 1536];
__device__ __align__(256) __nv_bfloat16 g_K3[3136 * 1536];
__device__ __align__(256) __nv_bfloat16 g_attn3[16000 * 640];
__device__ __align__(256) __nv_bfloat16 g_FKT[16 * 512 * 640];
// pipeline control
__device__ u32 g_tick;
__device__ u32 g_kdone[49];
__device__ u32 g_fdone[49];
__device__ u32 g_qdone;
__device__ u32 g_clfdone;
__device__ u32 g_sdone[16];
__device__ u32 g_adone[16];
__device__ u32 g_h1done;

// ---------------- HMMA m16n8k16 bf16 + ldmatrix + cp.async ----------------
__device__ __forceinline__ void mma16816(float4& c, const u32 a0, const u32 a1,
                                         const u32 a2, const u32 a3,
                                         const u32 b0, const u32 b1) {
    asm volatile(
        "mma.sync.aligned.m16n8k16.row.col.f32.bf16.bf16.f32 "
        "{%0,%1,%2,%3}, {%4,%5,%6,%7}, {%8,%9}, {%0,%1,%2,%3};"
        : "+f"(c.x), "+f"(c.y), "+f"(c.z), "+f"(c.w)
        : "r"(a0), "r"(a1), "r"(a2), "r"(a3), "r"(b0), "r"(b1));
}
__device__ __forceinline__ void ldsm_x4(u32& r0, u32& r1, u32& r2, u32& r3, u32 saddr) {
    asm volatile("ldmatrix.sync.aligned.m8n8.x4.shared.b16 {%0,%1,%2,%3}, [%4];"
        : "=r"(r0), "=r"(r1), "=r"(r2), "=r"(r3) : "r"(saddr));
}
__device__ __forceinline__ void cp16(u32 dst, const void* src) {
    asm volatile("cp.async.cg.shared.global [%0], [%1], 16;" :: "r"(dst), "l"(src));
}
#define CP_COMMIT() asm volatile("cp.async.commit_group;" ::: "memory")

#define HG_STAGE 15360
#define HG_SMEM  61440

__device__ __forceinline__ void emitK3(int r, int cc, float x0, float x1) {
    __nv_bfloat16 h0 = __float2bfloat16(x0);
    __nv_bfloat16 l0 = __float2bfloat16(x0 - __bfloat162float(h0));
    __nv_bfloat16 h1 = __float2bfloat16(x1);
    __nv_bfloat16 l1 = __float2bfloat16(x1 - __bfloat162float(h1));
    __nv_bfloat162 hp, lp;
    hp.x = h0; hp.y = h1; lp.x = l0; lp.y = l1;
    size_t base = (size_t)r * 1536 + cc;
    *reinterpret_cast<__nv_bfloat162*>(&g_K3[base])        = hp;
    *reinterpret_cast<__nv_bfloat162*>(&g_K3[base + 512])  = lp;
    *reinterpret_cast<__nv_bfloat162*>(&g_K3[base + 1024]) = hp;
}
__device__ __forceinline__ void emitFKT(int r, int j, float x0, float x1) {
    int b = r / 196, l = r - b * 196;
    __nv_bfloat16 h0 = __float2bfloat16(x0);
    __nv_bfloat16 l0 = __float2bfloat16(x0 - __bfloat162float(h0));
    __nv_bfloat16 h1 = __float2bfloat16(x1);
    __nv_bfloat16 l1 = __float2bfloat16(x1 - __bfloat162float(h1));
    size_t base0 = ((size_t)b * 512 + j) * 640 + l;
    g_FKT[base0]       = h0;
    g_FKT[base0 + 208] = l0;
    g_FKT[base0 + 416] = h0;
    size_t base1 = base0 + 640;
    g_FKT[base1]       = h1;
    g_FKT[base1 + 208] = l1;
    g_FKT[base1 + 416] = h1;
}

__device__ __forceinline__ int offA_of(int s, int dedup) {
    if (!dedup) return s << 5;
    return (s < 128) ? ((s & 63) << 5) : (2048 + ((s - 128) << 5));
}
__device__ __forceinline__ int offB_of(int s, int dedup) {
    if (!dedup) return s << 5;
    return (s < 64) ? (s << 5) : ((s < 128) ? (2048 + ((s - 64) << 5)) : ((s - 128) << 5));
}

__device__ __forceinline__ void dev_hgemm(char* smraw, int bxv, int byv,
    const __nv_bfloat16* __restrict__ A, int lda,
    const __nv_bfloat16* __restrict__ B, int ldb,
    const float* __restrict__ bias,
    float* __restrict__ C, int ldc,
    int M, int N, int K3, int do_relu, int mode, int dedup)
{
    int tid = threadIdx.x;
    int brow = byv * 64, bcol = bxv * 128;
    int warp = tid >> 5, lane = tid & 31;
    int wm = warp >> 2, wn = warp & 3;
    int grp = lane >> 2, tig = lane & 3;
    int alr = lane & 15, alc = (lane >> 4) & 1;
    int bl8 = lane & 7, bq = lane >> 3;

    int arow = tid >> 2, ak = (tid & 3) * 8;
    int ga_row = min(brow + arow, M - 1);
    const __nv_bfloat16* pa = A + (size_t)ga_row * lda + ak;
    int brw = tid >> 1, bk = (tid & 1) * 16;
    int gb_row = min(bcol + brw, N - 1);
    const __nv_bfloat16* pb = B + (size_t)gb_row * ldb + bk;

    u32 sbase = (u32)__cvta_generic_to_shared(smraw);
    u32 dAa = sbase + arow * 80 + ak * 2;
    u32 dBb = sbase + 5120 + brw * 80 + bk * 2;

    float4 acc[2][4];
#pragma unroll
    for (int i = 0; i < 2; i++)
#pragma unroll
        for (int j = 0; j < 4; j++) acc[i][j] = make_float4(0.f, 0.f, 0.f, 0.f);

    int nk = K3 >> 5;

#pragma unroll
    for (int s = 0; s < 3; s++) {
        u32 st = s * HG_STAGE;
        cp16(dAa + st, pa + offA_of(s, dedup));
        const __nv_bfloat16* qb = pb + offB_of(s, dedup);
        cp16(dBb + st, qb);  cp16(dBb + st + 16, qb + 8);
        CP_COMMIT();
    }

    for (int kt = 0; kt < nk; kt++) {
        int rem = nk - 1 - kt;
        if (rem >= 2)      asm volatile("cp.async.wait_group 2;" ::: "memory");
        else if (rem == 1) asm volatile("cp.async.wait_group 1;" ::: "memory");
        else               asm volatile("cp.async.wait_group 0;" ::: "memory");
        __syncthreads();

        if (kt + 3 < nk) {
            int s = kt + 3;
            u32 st = (s & 3) * HG_STAGE;
            cp16(dAa + st, pa + offA_of(s, dedup));
            const __nv_bfloat16* qb = pb + offB_of(s, dedup);
            cp16(dBb + st, qb);  cp16(dBb + st + 16, qb + 8);
            CP_COMMIT();
        }

        char* stg = smraw + (kt & 3) * HG_STAGE;
        __nv_bfloat16 (*As)[40] = reinterpret_cast<__nv_bfloat16(*)[40]>(stg);
        __nv_bfloat16 (*Bs)[40] = reinterpret_cast<__nv_bfloat16(*)[40]>(stg + 5120);

#pragma unroll
        for (int kk = 0; kk < 32; kk += 16) {
            u32 af[2][4], bfr[4][2];
#pragma unroll
            for (int mi = 0; mi < 2; mi++) {
                u32 sa = (u32)__cvta_generic_to_shared(
                    &As[wm * 32 + mi * 16 + alr][kk + alc * 8]);
                ldsm_x4(af[mi][0], af[mi][1], af[mi][2], af[mi][3], sa);
            }
#pragma unroll
            for (int np = 0; np < 2; np++) {
                u32 sb = (u32)__cvta_generic_to_shared(
                    &Bs[wn * 32 + np * 16 + (bq >> 1) * 8 + bl8][kk + (bq & 1) * 8]);
                ldsm_x4(bfr[np * 2][0], bfr[np * 2][1],
                        bfr[np * 2 + 1][0], bfr[np * 2 + 1][1], sb);
            }
#pragma unroll
            for (int mi = 0; mi < 2; mi++)
#pragma unroll
                for (int ni = 0; ni < 4; ni++)
                    mma16816(acc[mi][ni], af[mi][0], af[mi][1], af[mi][2], af[mi][3],
                             bfr[ni][0], bfr[ni][1]);
        }
    }

    if (mode == 0) {
#pragma unroll
        for (int mi = 0; mi < 2; mi++) {
            int r0 = brow + wm * 32 + mi * 16 + grp;
            int r1 = r0 + 8;
#pragma unroll
            for (int ni = 0; ni < 4; ni++) {
                int cc = bcol + wn * 32 + ni * 8 + tig * 2;
                float b0 = 0.f, b1 = 0.f;
                if (bias) {
                    if (cc < N)     b0 = bias[cc];
                    if (cc + 1 < N) b1 = bias[cc + 1];
                }
                float4 v = acc[mi][ni];
                float vx = v.x + b0, vy = v.y + b1, vz = v.z + b0, vw = v.w + b1;
                if (do_relu) {
                    vx = fmaxf(vx, 0.f); vy = fmaxf(vy, 0.f);
                    vz = fmaxf(vz, 0.f); vw = fmaxf(vw, 0.f);
                }
                if (r0 < M) {
                    if (cc < N)     C[(size_t)r0 * ldc + cc]     = vx;
                    if (cc + 1 < N) C[(size_t)r0 * ldc + cc + 1] = vy;
                }
                if (r1 < M) {
                    if (cc < N)     C[(size_t)r1 * ldc + cc]     = vz;
                    if (cc + 1 < N) C[(size_t)r1 * ldc + cc + 1] = vw;
                }
            }
        }
    } else {
#pragma unroll
        for (int mi = 0; mi < 2; mi++) {
            int r0 = brow + wm * 32 + mi * 16 + grp;
            int r1 = r0 + 8;
#pragma unroll
            for (int ni = 0; ni < 4; ni++) {
                int cc = bcol + wn * 32 + ni * 8 + tig * 2;
                float4 v = acc[mi][ni];
                if (cc < 512) {
                    float b0 = g_biasB[cc], b1 = g_biasB[cc + 1];
                    emitK3(r0, cc, v.x + b0, v.y + b1);
                    emitK3(r1, cc, v.z + b0, v.w + b1);
                } else {
                    int j = cc - 512;
                    emitFKT(r0, j, v.x, v.y);
                    emitFKT(r1, j, v.z, v.w);
                }
            }
        }
    }
}

// ---------------- device f32x2 SGEMM ----------------
typedef float STile[16][128];

__device__ __forceinline__ void dev_sgemm(char* smraw, int bxv, int byv,
    const float* __restrict__ A, int lda,
    const float* __restrict__ B, int ldb,
    const float* __restrict__ bias,
    float* __restrict__ C, int ldc,
    int M, int N, int K, int do_relu)
{
    STile* As = reinterpret_cast<STile*>(smraw);
    STile* Bs = reinterpret_cast<STile*>(smraw + 16384);
    int tid = threadIdx.x;
    int brow = byv * 128;
    int bcol = bxv * 128;

    int a_row = tid >> 1;
    int a_col = (tid & 1) * 8;
    int b_k   = tid >> 4;
    int b_col = (tid & 15) * 8;
    int ty = tid >> 4, tx = tid & 15;

    unsigned long long acc2[8][4];
#pragma unroll
    for (int i = 0; i < 8; i++)
#pragma unroll
        for (int j = 0; j < 4; j++) acc2[i][j] = 0ULL;

    int nk = (K + 15) >> 4;
    float4 pa0, pa1, pb0, pb1;

    {
        pa0 = make_float4(0.f,0.f,0.f,0.f); pa1 = pa0; pb0 = pa0; pb1 = pa0;
        if (brow + a_row < M) {
            const float* p = A + (size_t)(brow + a_row) * lda + a_col;
            if (a_col < K)     pa0 = *reinterpret_cast<const float4*>(p);
            if (a_col + 4 < K) pa1 = *reinterpret_cast<const float4*>(p + 4);
        }
        if (b_k < K) {
            const float* p = B + (size_t)b_k * ldb + bcol + b_col;
            if (bcol + b_col < N)     pb0 = *reinterpret_cast<const float4*>(p);
            if (bcol + b_col + 4 < N) pb1 = *reinterpret_cast<const float4*>(p + 4);
        }
        As[0][a_col+0][a_row] = pa0.x; As[0][a_col+1][a_row] = pa0.y;
        As[0][a_col+2][a_row] = pa0.z; As[0][a_col+3][a_row] = pa0.w;
        As[0][a_col+4][a_row] = pa1.x; As[0][a_col+5][a_row] = pa1.y;
        As[0][a_col+6][a_row] = pa1.z; As[0][a_col+7][a_row] = pa1.w;
        *reinterpret_cast<float4*>(&Bs[0][b_k][b_col])     = pb0;
        *reinterpret_cast<float4*>(&Bs[0][b_k][b_col + 4]) = pb1;
    }
    __syncthreads();

    for (int t = 0; t < nk; t++) {
        int buf = t & 1;
        int nxt = t + 1;
        if (nxt < nk) {
            int k0 = nxt << 4;
            pa0 = make_float4(0.f,0.f,0.f,0.f); pa1 = pa0; pb0 = pa0; pb1 = pa0;
            if (brow + a_row < M) {
                const float* p = A + (size_t)(brow + a_row) * lda + k0 + a_col;
                if (k0 + a_col < K)     pa0 = *reinterpret_cast<const float4*>(p);
                if (k0 + a_col + 4 < K) pa1 = *reinterpret_cast<const float4*>(p + 4);
            }
            if (k0 + b_k < K) {
                const float* p = B + (size_t)(k0 + b_k) * ldb + bcol + b_col;
                if (bcol + b_col < N)     pb0 = *reinterpret_cast<const float4*>(p);
                if (bcol + b_col + 4 < N) pb1 = *reinterpret_cast<const float4*>(p + 4);
            }
        }

#pragma unroll
        for (int kk = 0; kk < 16; kk++) {
            float4 a0 = *reinterpret_cast<const float4*>(&As[buf][kk][ty * 8]);
            float4 a1 = *reinterpret_cast<const float4*>(&As[buf][kk][ty * 8 + 4]);
            ulonglong2 bq0 = *reinterpret_cast<const ulonglong2*>(&Bs[buf][kk][tx * 8]);
            ulonglong2 bq1 = *reinterpret_cast<const ulonglong2*>(&Bs[buf][kk][tx * 8 + 4]);
            unsigned long long bb0 = bq0.x, bb1 = bq0.y, bb2 = bq1.x, bb3 = bq1.y;
            float av[8] = {a0.x, a0.y, a0.z, a0.w, a1.x, a1.y, a1.z, a1.w};
#pragma unroll
            for (int i = 0; i < 8; i++) {
                unsigned long long aa;
                unsigned int ab = __float_as_uint(av[i]);
                asm("mov.b64 %0, {%1, %1};" : "=l"(aa) : "r"(ab));
                asm("fma.rn.f32x2 %0, %1, %2, %0;" : "+l"(acc2[i][0]) : "l"(aa), "l"(bb0));
                asm("fma.rn.f32x2 %0, %1, %2, %0;" : "+l"(acc2[i][1]) : "l"(aa), "l"(bb1));
                asm("fma.rn.f32x2 %0, %1, %2, %0;" : "+l"(acc2[i][2]) : "l"(aa), "l"(bb2));
                asm("fma.rn.f32x2 %0, %1, %2, %0;" : "+l"(acc2[i][3]) : "l"(aa), "l"(bb3));
            }
        }

        if (nxt < nk) {
            int nb = nxt & 1;
            As[nb][a_col+0][a_row] = pa0.x; As[nb][a_col+1][a_row] = pa0.y;
            As[nb][a_col+2][a_row] = pa0.z; As[nb][a_col+3][a_row] = pa0.w;
            As[nb][a_col+4][a_row] = pa1.x; As[nb][a_col+5][a_row] = pa1.y;
            As[nb][a_col+6][a_row] = pa1.z; As[nb][a_col+7][a_row] = pa1.w;
            *reinterpret_cast<float4*>(&Bs[nb][b_k][b_col])     = pb0;
            *reinterpret_cast<float4*>(&Bs[nb][b_k][b_col + 4]) = pb1;
        }
        __syncthreads();
    }

#pragma unroll
    for (int i = 0; i < 8; i++) {
        int r = brow + ty * 8 + i;
        if (r >= M) continue;
#pragma unroll
        for (int j = 0; j < 4; j++) {
            unsigned long long v = acc2[i][j];
            float c0 = __uint_as_float((unsigned int)v);
            float c1 = __uint_as_float((unsigned int)(v >> 32));
            int c = bcol + tx * 8 + j * 2;
            if (c < N) {
                float t = c0;
                if (bias) t += bias[c];
                if (do_relu) t = fmaxf(t, 0.f);
                C[(size_t)r * ldc + c] = t;
            }
            if (c + 1 < N) {
                float t = c1;
                if (bias) t += bias[c + 1];
                if (do_relu) t = fmaxf(t, 0.f);
                C[(size_t)r * ldc + c + 1] = t;
            }
        }
    }
}

// ---------------- MEGA_side device pieces ----------------
__device__ void dev_pooled(const float* __restrict__ feats, int v) {
    int fb = v & 7;
    int rest = v >> 3;
    int b = rest & 15;
    int ch = rest >> 4;
    int f = fb * 256 + threadIdx.x;
    const float* p = feats + ((size_t)b * Lq + ch * 49) * FDq + f;
    float s = 0.f;
#pragma unroll 7
    for (int l = 0; l < 49; l++) s += p[(size_t)l * FDq];
    g_pooled4[((ch * 16) + b) * 2048 + f] = s;
}

__device__ void dev_cvtA2(const float* __restrict__ feats, int v) {
    long long base = (long long)v * 2048 + threadIdx.x;
#pragma unroll
    for (int u = 0; u < 8; u++) {
        long long i = base + u * 256;
        if (i < 3136LL * 4096) {
            int c = (int)(i & 4095);
            long long r = i >> 12;
            int k = c & 2047;
            float x = feats[r * 2048 + k];
            __nv_bfloat16 h = __float2bfloat16(x);
            g_A2[i] = (c >= 2048) ? __float2bfloat16(x - __bfloat162float(h)) : h;
        }
    }
}

__device__ void dev_cvtB2(const float* __restrict__ Wk, const float* __restrict__ Wf1,
                          const float* __restrict__ bk, int v) {
    if (v == 0) {
        for (int t = threadIdx.x; t < 1024; t += 256)
            g_biasB[t] = (t < 512) ? bk[t] : 0.f;
    }
    long long base = (long long)v * 2048 + threadIdx.x;
#pragma unroll
    for (int u = 0; u < 8; u++) {
        long long i = base + u * 256;
        if (i < 1024LL * 4096) {
            int c = (int)(i & 4095);
            int n = (int)(i >> 12);
            int k = c & 2047;
            float x = (n < 512) ? Wk[(size_t)k * 512 + n] : Wf1[(size_t)k * 512 + (n - 512)];
            __nv_bfloat16 h = __float2bfloat16(x);
            g_B2[i] = (c >= 2048) ? __float2bfloat16(x - __bfloat162float(h)) : h;
        }
    }
}

__device__ void dev_fkt_pad(int v) {
    long long base = (long long)v * 2048 + threadIdx.x;
#pragma unroll
    for (int u = 0; u < 8; u++) {
        long long i = base + u * 256;
        if (i < 16LL * 512 * 52) {
            int e = (int)(i % 52);
            long long row = i / 52;
            int pos = (e < 36) ? (e / 12) * 208 + 196 + (e % 12) : 624 + (e - 36);
            g_FKT[row * 640 + pos] = __float2bfloat16(0.f);
        }
    }
}

#define MS_POOLED  512
#define MS_Q       (MS_POOLED + 32)
#define MS_P       (MS_Q + 16)
#define MS_QM      (MS_P + 16)
#define MS_ZERO    (MS_QM + 3907)
#define MS_CVTA    (MS_ZERO + 6272)
#define MS_CVTB    (MS_CVTA + 2048)
#define MS_TOTAL   (MS_CVTB + 208)

__global__ __launch_bounds__(256) void mega_side(const float* __restrict__ feats,
                                                 const float* __restrict__ embed,
                                                 const float* __restrict__ W_query,
                                                 const float* __restrict__ b_query,
                                                 const float* __restrict__ Wr1,
                                                 const float* __restrict__ W_key,
                                                 const float* __restrict__ Wf1,
                                                 const float* __restrict__ b_key) {
    __shared__ __align__(16) char sm[32768];
    int f = blockIdx.x;
    if (f == 0 && threadIdx.x == 0) {
        g_tick = 0; g_qdone = 0; g_clfdone = 0; g_h1done = 0;
        for (int i = 0; i < 49; i++) { g_kdone[i] = 0; g_fdone[i] = 0; }
        for (int i = 0; i < 16; i++) { g_sdone[i] = 0; g_adone[i] = 0; }
    }
    if (f < MS_POOLED) {
        dev_pooled(feats, f);
    } else if (f < MS_Q) {
        int v = f - MS_POOLED;
        dev_sgemm(sm, v & 3, v >> 2, embed, 300, W_query, 512, b_query,
                  g_queries, 512, 1000, 512, 300, 0);
    } else if (f < MS_P) {
        int v = f - MS_Q;
        dev_sgemm(sm, v & 1, v >> 1, embed, 300, Wr1, 256, nullptr,
                  g_PQ, 512, 1000, 256, 300, 0);
    } else if (f < MS_QM) {
        int v = f - MS_P;
        dev_sgemm(sm, v & 1, v >> 1, embed, 300, Wr1 + 300 * 256, 256, nullptr,
                  g_PQ + 256, 512, 1000, 256, 300, 0);
    } else if (f < MS_ZERO) {
        int i = (f - MS_QM) * 256 + threadIdx.x;
        if (i < 1000 * 1000) g_prop[i] = 0.f;
    } else if (f < MS_CVTA) {
        dev_cvtA2(feats, f - MS_ZERO);
    } else if (f < MS_CVTB) {
        dev_cvtB2(W_key, Wf1, b_key, f - MS_CVTA);
    } else {
        dev_fkt_pad(f - MS_CVTB);
    }
}

// ---------------- MEGA_BIG pieces ----------------
__device__ void dev_clf(char* smraw, int v, const float* __restrict__ W_clf,
                        const float* __restrict__ b_clf, float* __restrict__ out_img) {
    float (*sp)[2048] = reinterpret_cast<float(*)[2048]>(smraw);
    int tid = threadIdx.x;
    int bx = v & 3;
    int bg = (v >> 2) * 4;
    for (int i = tid; i < 4 * 2048; i += 256) {
        int g = i >> 11, ff = i & 2047;
        int b = bg + g;
        float s = g_pooled4[(0 * 16 + b) * 2048 + ff] + g_pooled4[(1 * 16 + b) * 2048 + ff]
                + g_pooled4[(2 * 16 + b) * 2048 + ff] + g_pooled4[(3 * 16 + b) * 2048 + ff];
        sp[g][ff] = s * (1.f / 196.f);
    }
    __syncthreads();
    int c = bx * 256 + tid;
    if (c < NIMGq) {
        float a0 = b_clf[c], a1 = a0, a2 = a0, a3 = a0;
#pragma unroll 4
        for (int f = 0; f < 2048; f++) {
            float w = W_clf[(size_t)f * NIMGq + c];
            a0 = fmaf(sp[0][f], w, a0);
            a1 = fmaf(sp[1][f], w, a1);
            a2 = fmaf(sp[2][f], w, a2);
            a3 = fmaf(sp[3][f], w, a3);
        }
        out_img[(bg + 0) * NIMGq + c] = a0;
        out_img[(bg + 1) * NIMGq + c] = a1;
        out_img[(bg + 2) * NIMGq + c] = a2;
        out_img[(bg + 3) * NIMGq + c] = a3;
    }
}

__device__ void dev_cvtQ3(int v) {
    long long base = (long long)v * 2048 + threadIdx.x;
#pragma unroll
    for (int u = 0; u < 8; u++) {
        long long i = base + u * 256;
        if (i < 1000LL * 1536) {
            int c = (int)(i % 1536);
            long long r = i / 1536;
            int seg = c >> 9, k = c & 511;
            float x = g_queries[r * 512 + k];
            __nv_bfloat16 h = __float2bfloat16(x);
            g_Q3[i] = (seg == 2) ? __float2bfloat16(x - __bfloat162float(h)) : h;
        }
    }
}

__device__ void dev_edge(int v, const int* __restrict__ edges, const float* __restrict__ br1,
                         const float* __restrict__ Wr2, const float* __restrict__ br2, int E) {
    int warp = (int)threadIdx.x >> 5;
    int lane = threadIdx.x & 31;
#pragma unroll
    for (int u = 0; u < 8; u++) {
        int e = v * 64 + u * 8 + warp;
        if (e >= E) break;
        int s = edges[e];
        int d = edges[E + e];
        const float* Pr = g_PQ + (size_t)s * 512;
        const float* Qr = g_PQ + (size_t)d * 512 + 256;
        float acc = 0.f;
#pragma unroll
        for (int i = 0; i < 8; i++) {
            int j = lane + 32 * i;
            float h = fmaxf(Pr[j] + Qr[j] + br1[j], 0.f);
            acc = fmaf(h, Wr2[j], acc);
        }
        for (int o = 16; o; o >>= 1) acc += __shfl_xor_sync(0xffffffffu, acc, o);
        if (lane == 0) atomicAdd(&g_prop[(size_t)s * 1000 + d], tanhf(acc + br2[0]));
    }
}

__device__ void dev_softmax1000(char* smraw, int b, float* __restrict__ base) {
    float* sv = reinterpret_cast<float*>(smraw);
    float* red = reinterpret_cast<float*>(smraw) + 1000;
    int tid = threadIdx.x;
    float* row = base + (size_t)b * 1000;
    float m = -1e30f;
    for (int i = tid; i < 1000; i += 256) { float x = row[i]; sv[i] = x; m = fmaxf(m, x); }
    for (int o = 16; o; o >>= 1) m = fmaxf(m, __shfl_xor_sync(0xffffffffu, m, o));
    if ((tid & 31) == 0) red[tid >> 5] = m;
    __syncthreads();
    float bm = red[0];
#pragma unroll
    for (int i = 1; i < 8; i++) bm = fmaxf(bm, red[i]);
    float s = 0.f;
    for (int i = tid; i < 1000; i += 256) { float e = expf(sv[i] - bm); sv[i] = e; s += e; }
    for (int o = 16; o; o >>= 1) s += __shfl_xor_sync(0xffffffffu, s, o);
    __syncthreads();
    if ((tid & 31) == 0) red[tid >> 5] = s;
    __syncthreads();
    float bs = 0.f;
#pragma unroll
    for (int i = 0; i < 8; i++) bs += red[i];
    float inv = 1.f / bs;
    for (int i = tid; i < 1000; i += 256) row[i] = sv[i] * inv;
}

__device__ void dev_softmax196(int v, float* __restrict__ attn) {
    int z = v / 125;
    int vv = v - z * 125;
    int warp = (int)threadIdx.x >> 5;
    int lane = threadIdx.x & 31;
    int gw = z * 1000 + vv * 8 + warp;
    const float* src = g_scores + (size_t)gw * Lq;
    float val[7];
    float m = -1e30f;
#pragma unroll
    for (int i = 0; i < 7; i++) {
        int j = lane + 32 * i;
        val[i] = (j < Lq) ? src[j] : -1e30f;
        m = fmaxf(m, val[i]);
    }
    for (int o = 16; o; o >>= 1) m = fmaxf(m, __shfl_xor_sync(0xffffffffu, m, o));
    float s = 0.f;
#pragma unroll
    for (int i = 0; i < 7; i++) {
        int j = lane + 32 * i;
        val[i] = (j < Lq) ? expf(val[i] - m) : 0.f;
        s += val[i];
    }
    for (int o = 16; o; o >>= 1) s += __shfl_xor_sync(0xffffffffu, s, o);
    float inv = 1.f / s;
    size_t base = (size_t)gw * 640;
#pragma unroll
    for (int i = 0; i < 7; i++) {
        int j = lane + 32 * i;
        if (j < Lq) {
            float e = val[i] * inv;
            attn[(size_t)gw * Lq + j] = e;
            __nv_bfloat16 h = __float2bfloat16(e);
            __nv_bfloat16 lo = __float2bfloat16(e - __bfloat162float(h));
            g_attn3[base + 0 * 208 + j] = h;
            g_attn3[base + 1 * 208 + j] = h;
            g_attn3[base + 2 * 208 + j] = lo;
        }
    }
    __nv_bfloat16 zz = __float2bfloat16(0.f);
#pragma unroll
    for (int e2 = 0; e2 < 2; e2++) {
        int t = lane + e2 * 32;
        if (t < 52) {
            int pos = (t < 36) ? (t / 12) * 208 + 196 + (t % 12) : 624 + (t - 36);
            g_attn3[base + pos] = zz;
        }
    }
}

// h0 -> g_hA [b*1000+n][5]
__device__ void dev_h0(int v, const float* __restrict__ Wf2, const float* __restrict__ bf2) {
    int gw = v * 8 + ((int)threadIdx.x >> 5);
    int lane = threadIdx.x & 31;
    if (gw >= 16000) return;
    const float* row = g_H1 + (size_t)gw * 512;
    float acc[5] = {0.f, 0.f, 0.f, 0.f, 0.f};
#pragma unroll
    for (int i = 0; i < 16; i++) {
        int j = lane + 32 * i;
        float vv = row[j];
#pragma unroll
        for (int d = 0; d < 5; d++) acc[d] = fmaf(vv, Wf2[j * 5 + d], acc[d]);
    }
#pragma unroll
    for (int d = 0; d < 5; d++)
        for (int o = 16; o; o >>= 1) acc[d] += __shfl_xor_sync(0xffffffffu, acc[d], o);
    if (lane == 0) {
#pragma unroll
        for (int d = 0; d < 5; d++) g_hA[gw * 5 + d] = acc[d] + bf2[d];
    }
}

__device__ __forceinline__ void spin_ge(volatile u32* p, u32 target) {
    while (*p < target) __nanosleep(128);
}

// ticket layout:
// [feats 392][clf 16][cvtQ3 750][edges NE][scores 512][sm1000 16][sm196 2000][H1 1024][h0 2000]
__global__ __launch_bounds__(256) void mega_big(const float* __restrict__ W_clf,
                                                const float* __restrict__ b_clf,
                                                float* __restrict__ out_img,
                                                const int* __restrict__ edges,
                                                const float* __restrict__ br1,
                                                const float* __restrict__ Wr2,
                                                const float* __restrict__ br2,
                                                float* __restrict__ out_attn,
                                                const float* __restrict__ bf1,
                                                const float* __restrict__ Wf2,
                                                const float* __restrict__ bf2,
                                                int E, int NE) {
    extern __shared__ __align__(16) char smdyn[];
    __shared__ u32 s_tick;
    if (threadIdx.x == 0) s_tick = atomicAdd(&g_tick, 1u);
    __syncthreads();
    int f = (int)s_tick;

    int T_CLF = 392 + 16;
    int T_Q    = T_CLF + 750;
    int T_E    = T_Q + NE;
    int T_SC   = T_E + 512;
    int T_SM1K = T_SC + 16;
    int T_SM   = T_SM1K + 2000;
    int T_H1   = T_SM + 1024;

    if (f < 392) {
        int bx = f & 7, by = f >> 3;
        dev_hgemm(smdyn, bx, by, g_A2, 4096, g_B2, 4096, nullptr,
                  nullptr, 0, 3136, 1024, 6144, 0, 1, 1);
        __threadfence();
        __syncthreads();
        if (threadIdx.x == 0) {
            if (bx < 4) atomicAdd(&g_kdone[by], 1u);
            else        atomicAdd(&g_fdone[by], 1u);
        }
    } else if (f < T_CLF) {
        dev_clf(smdyn, f - 392, W_clf, b_clf, out_img);
        __threadfence();
        __syncthreads();
        if (threadIdx.x == 0) atomicAdd(&g_clfdone, 1u);
    } else if (f < T_Q) {
        dev_cvtQ3(f - T_CLF);
        __threadfence();
        __syncthreads();
        if (threadIdx.x == 0) atomicAdd(&g_qdone, 1u);
    } else if (f < T_E) {
        dev_edge(f - T_Q, edges, br1, Wr2, br2, E);
    } else if (f < T_SC) {
        int v = f - T_E;
        int bx = v & 1, by = (v >> 1) & 15, z = v >> 5;
        if (threadIdx.x == 0) {
            spin_ge(&g_qdone, 750u);
            int t0 = (196 * z) >> 6;
            int t3 = (196 * z + 195) >> 6;
            for (int t = t0; t <= t3; t++) spin_ge(&g_kdone[t], 4u);
        }
        __syncthreads();
        __threadfence();
        dev_hgemm(smdyn, bx, by,
                  g_Q3, 1536,
                  g_K3 + (size_t)z * 196 * 1536, 1536, nullptr,
                  g_scores + (size_t)z * 1000 * 196, 196,
                  1000, 196, 1536, 0, 0, 0);
        __threadfence();
        __syncthreads();
        if (threadIdx.x == 0) atomicAdd(&g_sdone[z], 1u);
    } else if (f < T_SM1K) {
        if (threadIdx.x == 0) spin_ge(&g_clfdone, 16u);
        __syncthreads();
        __threadfence();
        dev_softmax1000(smdyn, f - T_SC, out_img);
    } else if (f < T_SM) {
        int v = f - T_SM1K;
        int z = v / 125;
        if (threadIdx.x == 0) spin_ge(&g_sdone[z], 32u);
        __syncthreads();
        __threadfence();
        dev_softmax196(v, out_attn);
        __threadfence();
        __syncthreads();
        if (threadIdx.x == 0) atomicAdd(&g_adone[z], 1u);
    } else if (f < T_H1) {
        int v = f - T_SM;
        int bx = v & 3, by = (v >> 2) & 15, z = v >> 6;
        if (threadIdx.x == 0) {
            spin_ge(&g_adone[z], 125u);
            int t0 = (196 * z) >> 6;
            int t3 = (196 * z + 195) >> 6;
            for (int t = t0; t <= t3; t++) spin_ge(&g_fdone[t], 4u);
        }
        __syncthreads();
        __threadfence();
        dev_hgemm(smdyn, bx, by,
                  g_attn3 + (size_t)z * 1000 * 640, 640,
                  g_FKT + (size_t)z * 512 * 640, 640, bf1,
                  g_H1 + (size_t)z * 1000 * 512, 512,
                  1000, 512, 640, 1, 0, 0);
        __threadfence();
        __syncthreads();
        if (threadIdx.x == 0) atomicAdd(&g_h1done, 1u);
    } else {
        if (threadIdx.x == 0) spin_ge(&g_h1done, 1024u);
        __syncthreads();
        __threadfence();
        dev_h0(f - T_H1, Wf2, bf2);
    }
}

// ---------------- GNN + output ----------------
// fused msg+GRU, 2 batches per block. grid (16, 8), 320 threads (64 n x 5 d).
// double-buffered sp tiles (1 barrier per tile) + dual accumulators.
__global__ __launch_bounds__(320) void msg_gru_kernel(const float* __restrict__ Wih,
                                                      const float* __restrict__ bih,
                                                      const float* __restrict__ Whh,
                                                      const float* __restrict__ bhh,
                                                      int sel) {
    __shared__ float sp[2][64][65];
    __shared__ float sh[2][2][320];
    __shared__ float sx[2][64][5];
    const float* hin = sel ? g_hB : g_hA;
    float* hout = sel ? g_hA : g_hB;
    int b0 = blockIdx.y * 2;
    int n0 = blockIdx.x * 64;
    int tid = threadIdx.x;
    int nl = tid / 5, d = tid % 5;

    // load tile 0 into buf 0
    {
        int mlen = 64;
        for (int idx = tid; idx < 64 * 64; idx += 320) {
            int r = idx >> 6, c = idx & 63;
            sp[0][r][c] = (c < mlen) ? g_prop[(size_t)(n0 + r) * 1000 + c] : 0.f;
        }
        sh[0][0][tid] = hin[((size_t)(b0 + 0) * 1000) * 5 + tid];
        sh[0][1][tid] = hin[((size_t)(b0 + 1) * 1000) * 5 + tid];
    }
    __syncthreads();

    float a0e = 0.f, a0o = 0.f, a1e = 0.f, a1o = 0.f;
    for (int tt = 0; tt < 16; tt++) {
        int buf = tt & 1;
        if (tt + 1 < 16) {
            int m0 = (tt + 1) * 64;
            int mlen = min(64, 1000 - m0);
            int nb = buf ^ 1;
            for (int idx = tid; idx < 64 * 64; idx += 320) {
                int r = idx >> 6, c = idx & 63;
                sp[nb][r][c] = (c < mlen) ? g_prop[(size_t)(n0 + r) * 1000 + m0 + c] : 0.f;
            }
            sh[nb][0][tid] = (tid < mlen * 5) ? hin[((size_t)(b0 + 0) * 1000 + m0) * 5 + tid] : 0.f;
            sh[nb][1][tid] = (tid < mlen * 5) ? hin[((size_t)(b0 + 1) * 1000 + m0) * 5 + tid] : 0.f;
        }
#pragma unroll 8
        for (int mm = 0; mm < 64; mm += 2) {
            float p0 = sp[buf][nl][mm];
            float p1 = sp[buf][nl][mm + 1];
            a0e = fmaf(p0, sh[buf][0][mm * 5 + d], a0e);
            a1e = fmaf(p0, sh[buf][1][mm * 5 + d], a1e);
            a0o = fmaf(p1, sh[buf][0][(mm + 1) * 5 + d], a0o);
            a1o = fmaf(p1, sh[buf][1][(mm + 1) * 5 + d], a1o);
        }
        __syncthreads();
    }
    sx[0][nl][d] = tanhf(a0e + a0o);
    sx[1][nl][d] = tanhf(a1e + a1o);
    __syncthreads();

    int n = n0 + nl;
    if (n >= 1000) return;
#pragma unroll
    for (int g = 0; g < 2; g++) {
        size_t roff = ((size_t)(b0 + g) * 1000 + n) * 5;
        float x[5], h[5];
#pragma unroll
        for (int k = 0; k < 5; k++) { x[k] = sx[g][nl][k]; h[k] = hin[roff + k]; }
        float ir = bih[d], iz = bih[5 + d], in_ = bih[10 + d];
        float hr = bhh[d], hz = bhh[5 + d], hn = bhh[10 + d];
#pragma unroll
        for (int k = 0; k < 5; k++) {
            ir = fmaf(x[k], Wih[d * 5 + k], ir);
            iz = fmaf(x[k], Wih[(5 + d) * 5 + k], iz);
            in_ = fmaf(x[k], Wih[(10 + d) * 5 + k], in_);
            hr = fmaf(h[k], Whh[d * 5 + k], hr);
            hz = fmaf(h[k], Whh[(5 + d) * 5 + k], hz);
            hn = fmaf(h[k], Whh[(10 + d) * 5 + k], hn);
        }
        float rr = 1.f / (1.f + expf(-(ir + hr)));
        float zz = 1.f / (1.f + expf(-(iz + hz)));
        float nn = tanhf(in_ + rr * hn);
        hout[roff + d] = (1.f - zz) * nn + zz * h[d];
    }
}

__global__ void out_kernel(const float* __restrict__ Wo1, const float* __restrict__ bo1,
                           const float* __restrict__ Wo2, const float* __restrict__ bo2,
                           float* __restrict__ out) {
    int gw = (blockIdx.x * blockDim.x + threadIdx.x) >> 5;
    int lane = threadIdx.x & 31;
    if (gw >= 16000) return;
    float h[5];
#pragma unroll
    for (int d = 0; d < 5; d++) h[d] = g_hB[gw * 5 + d];
    float acc = 0.f;
#pragma unroll
    for (int i = 0; i < 16; i++) {
        int j = lane + 32 * i;
        float t = bo1[j];
#pragma unroll
        for (int d = 0; d < 5; d++) t = fmaf(h[d], Wo1[d * 512 + j], t);
        acc = fmaf(fmaxf(t, 0.f), Wo2[j], acc);
    }
    for (int o = 16; o; o >>= 1) acc += __shfl_xor_sync(0xffffffffu, acc, o);
    if (lane == 0) out[gw] = acc + bo2[0];
}

// ---------------- launcher ----------------
extern "C" void kernel_launch(void* const* d_in, const int* in_sizes, int n_in,
                              void* d_out, int out_size) {
    const float* feats  = (const float*)d_in[0];
    const float* embed  = (const float*)d_in[1];
    const int*   edges  = (const int*)d_in[2];
    const float* W_key  = (const float*)d_in[3];
    const float* b_key  = (const float*)d_in[4];
    const float* W_query= (const float*)d_in[5];
    const float* b_query= (const float*)d_in[6];
    const float* Wf1    = (const float*)d_in[7];
    const float* bf1    = (const float*)d_in[8];
    const float* Wf2    = (const float*)d_in[9];
    const float* bf2    = (const float*)d_in[10];
    const float* Wr1    = (const float*)d_in[11];
    const float* br1    = (const float*)d_in[12];
    const float* Wr2    = (const float*)d_in[13];
    const float* br2    = (const float*)d_in[14];
    const float* Wo1    = (const float*)d_in[15];
    const float* bo1    = (const float*)d_in[16];
    const float* Wo2    = (const float*)d_in[17];
    const float* bo2    = (const float*)d_in[18];
    const float* W_ih   = (const float*)d_in[19];
    const float* b_ih   = (const float*)d_in[20];
    const float* W_hh   = (const float*)d_in[21];
    const float* b_hh   = (const float*)d_in[22];
    const float* W_clf  = (const float*)d_in[23];
    const float* b_clf  = (const float*)d_in[24];

    float* out        = (float*)d_out;
    float* out_logits = out;
    float* out_attn   = out + 16000;
    float* out_img    = out + 16000 + 16 * 1000 * 196;

    int E = in_sizes[2] / 2;
    int NE = (E + 63) / 64;

    static int smem_set = 0;
    if (!smem_set) {
        cudaFuncSetAttribute(mega_big, cudaFuncAttributeMaxDynamicSharedMemorySize, HG_SMEM);
        smem_set = 1;
    }

    // 1. MEGA_side: pooled | queries | P | Qm | zero_prop | cvtA2 | cvtB2 | fkt_pad (+flags)
    mega_side<<<MS_TOTAL, 256>>>(feats, embed, W_query, b_query, Wr1, W_key, Wf1, b_key);
    // 2. MEGA_BIG (ticketed): feats -> K3/FKT | clf | Q3 | edges | scores | sm1000 | sm196 | H1 | h0
    int nbig = 1158 + NE + 512 + 16 + 2000 + 1024 + 2000;
    mega_big<<<nbig, 256, HG_SMEM>>>(W_clf, b_clf, out_img, edges, br1, Wr2, br2,
                                     out_attn, bf1, Wf2, bf2, E, NE);
    // 3-7. GNN steps (2 batches per block, double-buffered)
    for (int t = 0; t < TMAXq; t++) {
        int sel = t & 1;
        msg_gru_kernel<<<dim3(16, 8), 320>>>(W_ih, b_ih, W_hh, b_hh, sel);
    }
    // 8. output MLP
    out_kernel<<<2000, 256>>>(Wo1, bo1, Wo2, bo2, out_logits);

    (void)n_in; (void)out_size;
}